// round 6
// baseline (speedup 1.0000x reference)
#include <cuda_runtime.h>
#include <math.h>
#include <stdint.h>

#define VGRID   100
#define NBATCH  8
#define NPTS    65536
#define NPOINTS (NBATCH * NPTS)                   // 524288
#define NVOX    (NBATCH * VGRID * VGRID * VGRID)  // 8,000,000
#define COUT    10
#define NWORDS  (NVOX / 32)                       // 250,000
#define NSCAT   512                               // scatter blocks (NPOINTS/4/256)
#define NPRE    (NVOX / 256)                      // 31250 prefill blocks

// 32B record per voxel: lo=[x,y,z,f0], hi=[f1,f2,cnt,pad].
// Zero at module load; sparse_finalize self-cleans touched records + bitmap
// (thread owns its word -> race-free, graph-replay safe).
__device__ __align__(32) float4 g_acc[(size_t)NVOX * 2];
__device__ uint32_t g_bits[NWORDS];

// ---------------------------------------------------------------------------
// Fused kernel: blocks [0,512) scatter points; blocks [512, 512+31250) write
// the "empty voxel" pattern for ALL voxels. Disjoint memory -> free overlap:
// latency-bound atomics hide inside the DRAM-bound 320MB pattern write.
// ---------------------------------------------------------------------------
__global__ void fused_kernel(const float4* __restrict__ coords4,
                             const float4* __restrict__ feats4,
                             float* __restrict__ out) {
    __shared__ float sh[256 * COUT];

    if (blockIdx.x < NSCAT) {
        // ---- scatter: 4 points/thread, 6x LDG.128, 3 atomics/point ----
        int t = blockIdx.x * 256 + threadIdx.x;      // < NPOINTS/4
        const float RES = 1.0f / 100.0f;

        float4 c0 = coords4[3 * t], c1 = coords4[3 * t + 1], c2 = coords4[3 * t + 2];
        float4 g0 = feats4 [3 * t], g1 = feats4 [3 * t + 1], g2 = feats4 [3 * t + 2];

        float cx[4] = {c0.x, c0.w, c1.z, c2.y};
        float cy[4] = {c0.y, c1.x, c1.w, c2.z};
        float cz[4] = {c0.z, c1.y, c2.x, c2.w};
        float fa[4] = {g0.x, g0.w, g1.z, g2.y};
        float fb[4] = {g0.y, g1.x, g1.w, g2.z};
        float fc[4] = {g0.z, g1.y, g2.x, g2.w};

        int b = t >> 14;   // (4t)/65536: 4 points never straddle a batch

        #pragma unroll
        for (int j = 0; j < 4; j++) {
            float x = cx[j], y = cy[j], z = cz[j];
            int ix = (int)floorf((x + RES) / RES);
            int iy = (int)floorf((y + RES) / RES);
            int iz = (int)floorf((z + RES) / RES);
            if (ix < 1 || ix > VGRID || iy < 1 || iy > VGRID ||
                iz < 1 || iz > VGRID)
                continue;
            int v = (((b * VGRID + (ix - 1)) * VGRID + (iy - 1)) * VGRID + (iz - 1));
            float4* rec = g_acc + (size_t)v * 2;
            asm volatile("red.global.add.v4.f32 [%0], {%1, %2, %3, %4};"
                         :: "l"(rec), "f"(x), "f"(y), "f"(z), "f"(fa[j]) : "memory");
            asm volatile("red.global.add.v4.f32 [%0], {%1, %2, %3, %4};"
                         :: "l"(rec + 1), "f"(fb[j]), "f"(fc[j]), "f"(1.0f), "f"(0.0f)
                         : "memory");
            atomicOr(&g_bits[v >> 5], 1u << (v & 31));
        }
    } else {
        // ---- prefill: empty pattern for 256 voxels/block, pure write ----
        int v = (blockIdx.x - NSCAT) * 256 + threadIdx.x;   // < NVOX

        // v = ((b*100 + i)*100 + j)*100 + k
        int k = v % VGRID;
        int t = v / VGRID;
        int j = t % VGRID;
        int i = (t / VGRID) % VGRID;

        float* r = sh + threadIdx.x * COUT;
        r[0] = 0.f; r[1] = 0.f; r[2] = 0.f; r[3] = 0.f; r[4] = 0.f; r[5] = 0.f;
        r[6] = (float)i * 0.01f;
        r[7] = (float)j * 0.01f;
        r[8] = (float)k * 0.01f;
        r[9] = 0.f;

        __syncthreads();

        // 2560 floats = 640 float4 per block, plain coalesced STG.128
        float4* dst = reinterpret_cast<float4*>(
            out + (size_t)(blockIdx.x - NSCAT) * 256 * COUT);
        const float4* src = reinterpret_cast<const float4*>(sh);
        #pragma unroll
        for (int q = 0; q < 640; q += 256) {
            int idx = q + threadIdx.x;
            if (idx < 640) dst[idx] = src[idx];
        }
    }
}

// ---------------------------------------------------------------------------
// Sparse finalize: one thread per bitmap word; walk set bits (~2/word avg),
// read record, overwrite that voxel's 40B output, self-clean.
// ---------------------------------------------------------------------------
__global__ void sparse_finalize_kernel(float* __restrict__ out) {
    int w = blockIdx.x * 256 + threadIdx.x;
    if (w >= NWORDS) return;

    uint32_t word = g_bits[w];
    if (word == 0u) return;
    g_bits[w] = 0u;                         // self-clean (thread owns word)

    const float4 z4 = make_float4(0.f, 0.f, 0.f, 0.f);

    while (word) {
        int bit = __ffs(word) - 1;
        word &= word - 1;
        int v = (w << 5) + bit;

        float4 lo = g_acc[2 * (size_t)v];
        float4 hi = g_acc[2 * (size_t)v + 1];
        g_acc[2 * (size_t)v]     = z4;      // self-clean record
        g_acc[2 * (size_t)v + 1] = z4;

        float inv = 1.0f / hi.z;            // occupied => cnt >= 1

        int k = v % VGRID;
        int t = v / VGRID;
        int j = t % VGRID;
        int i = (t / VGRID) % VGRID;

        float2* o2 = reinterpret_cast<float2*>(out + (size_t)v * COUT);  // 8B-aligned
        o2[0] = make_float2(lo.x * inv, lo.y * inv);
        o2[1] = make_float2(lo.z * inv, lo.w * inv);
        o2[2] = make_float2(hi.x * inv, hi.y * inv);
        o2[3] = make_float2((float)i * 0.01f, (float)j * 0.01f);
        o2[4] = make_float2((float)k * 0.01f, 1.0f);
    }
}

// ---------------------------------------------------------------------------
extern "C" void kernel_launch(void* const* d_in, const int* in_sizes, int n_in,
                              void* d_out, int out_size) {
    const float4* coords4 = (const float4*)d_in[0];
    const float4* feats4  = (const float4*)d_in[1];
    float* out = (float*)d_out;

    fused_kernel<<<NSCAT + NPRE, 256>>>(coords4, feats4, out);
    sparse_finalize_kernel<<<(NWORDS + 255) / 256, 256>>>(out);
}